// round 13
// baseline (speedup 1.0000x reference)
#include <cuda_runtime.h>
#include <math.h>

#define B        512
#define IN       1024
#define NN       4224
#define TOTAL    5248
#define KB       128
#define NBLK     33
#define OUT_N    128
#define SC       2.8853900817779268f   // 2*log2(e)

// Device-global scratch (allocation-free rule). Replay-safe: every buffer is
// overwritten each run, or zeroed before accumulation (g_upd).
__device__ float g_ph  [(size_t)4 * B * NN];          // split-K preA partials
__device__ float g_upd [(size_t)B * NN];              // far-update accumulator
__device__ float g_hall[(size_t)B * NN];              // published h per node
__device__ float g_n1  [(size_t)B * NN];              // near contrib from b-1 (overwrite)
__device__ float g_n2  [(size_t)B * NN];              // near contrib from b-2 (overwrite)
__device__ float g_tri [(size_t)NBLK * KB * KB];      // [b][t][i] scaled, zeroed t>=i
__device__ float g_nw  [(size_t)(NBLK - 1) * KB * KB];// [b][t][n] block b+1 weights
__device__ float g_nw2 [(size_t)(NBLK - 2) * KB * KB];// [b][t][n] block b+2 weights

// ---------------------------------------------------------------------------
// GEMM core (validated R6/R8 form: FFMA2 + pack movs, single-buffered smem).
// C[r][cjbase+n] (+)= sum_k A[r][aoff+k] * Wsub[n*TOTAL + k];  C row stride NN.
// ---------------------------------------------------------------------------
#define BM 128
#define BN 64
#define BK 16
#define AS 132
#define BS 68

__device__ __forceinline__ void
gemm_core(const float* __restrict__ A, int lda, int aoff,
          const float* __restrict__ Wsub, float* __restrict__ C,
          int cjbase, int kc, bool accum, float* As_, float* Bs_)
{
    int m0 = blockIdx.x * BM;
    int n0 = blockIdx.y * BN;
    int tid = threadIdx.x;
    int tx = tid & 15;
    int ty = tid >> 4;

    int a_r = tid >> 1;
    int a_k = (tid & 1) * 8;
    int b_r = tid >> 2;
    int b_k = (tid & 3) * 4;

    unsigned long long acc2[4][4];
#pragma unroll
    for (int i = 0; i < 4; i++)
#pragma unroll
        for (int j = 0; j < 4; j++) acc2[i][j] = 0ull;

    for (int kk = 0; kk < kc; kk += BK) {
        float4 a0 = *(const float4*)(A + (size_t)(m0 + a_r) * lda + aoff + kk + a_k);
        float4 a1 = *(const float4*)(A + (size_t)(m0 + a_r) * lda + aoff + kk + a_k + 4);
        As_[(a_k + 0) * AS + a_r] = a0.x;
        As_[(a_k + 1) * AS + a_r] = a0.y;
        As_[(a_k + 2) * AS + a_r] = a0.z;
        As_[(a_k + 3) * AS + a_r] = a0.w;
        As_[(a_k + 4) * AS + a_r] = a1.x;
        As_[(a_k + 5) * AS + a_r] = a1.y;
        As_[(a_k + 6) * AS + a_r] = a1.z;
        As_[(a_k + 7) * AS + a_r] = a1.w;

        float4 bv = *(const float4*)(Wsub + (size_t)(n0 + b_r) * TOTAL + kk + b_k);
        Bs_[(b_k + 0) * BS + b_r] = bv.x;
        Bs_[(b_k + 1) * BS + b_r] = bv.y;
        Bs_[(b_k + 2) * BS + b_r] = bv.z;
        Bs_[(b_k + 3) * BS + b_r] = bv.w;

        __syncthreads();

#pragma unroll
        for (int k = 0; k < BK; k++) {
            float a[8], b[4];
            *(float4*)&a[0] = *(const float4*)&As_[k * AS + ty * 8];
            *(float4*)&a[4] = *(const float4*)&As_[k * AS + ty * 8 + 4];
            *(float4*)&b[0] = *(const float4*)&Bs_[k * BS + tx * 4];

            unsigned long long ap[4], bb[4];
#pragma unroll
            for (int i = 0; i < 4; i++)
                asm("mov.b64 %0, {%1, %2};"
                    : "=l"(ap[i]) : "f"(a[2 * i]), "f"(a[2 * i + 1]));
#pragma unroll
            for (int j = 0; j < 4; j++)
                asm("mov.b64 %0, {%1, %2};"
                    : "=l"(bb[j]) : "f"(b[j]), "f"(b[j]));

#pragma unroll
            for (int i = 0; i < 4; i++)
#pragma unroll
                for (int j = 0; j < 4; j++)
                    asm("fma.rn.f32x2 %0, %1, %2, %0;"
                        : "+l"(acc2[i][j]) : "l"(ap[i]), "l"(bb[j]));
        }
        __syncthreads();
    }

#pragma unroll
    for (int i = 0; i < 4; i++) {
        float v0[4], v1[4];
#pragma unroll
        for (int j = 0; j < 4; j++)
            asm("mov.b64 {%0, %1}, %2;"
                : "=f"(v0[j]), "=f"(v1[j]) : "l"(acc2[i][j]));

        float* c0 = C + (size_t)(m0 + ty * 8 + 2 * i) * NN + cjbase + n0 + tx * 4;
        float* c1 = c0 + NN;
        if (accum) {
#pragma unroll
            for (int j = 0; j < 4; j++) { c0[j] += v0[j]; c1[j] += v1[j]; }
        } else {
            float4 w0, w1;
            w0.x = v0[0]; w0.y = v0[1]; w0.z = v0[2]; w0.w = v0[3];
            w1.x = v1[0]; w1.y = v1[1]; w1.z = v1[2]; w1.w = v1[3];
            *(float4*)c0 = w0;
            *(float4*)c1 = w1;
        }
    }
}

// preA split-K, CHUNKED over node columns: chunk covers BN-columns
// [y0*64, (y0+gridDim.y)*64). g_ph[z] = x[:, z*256:...] @ W[cols, z*256:...]^T
__global__ void __launch_bounds__(256)
prea_kernel(const float* __restrict__ x, const float* __restrict__ W, int y0)
{
    __shared__ float As_[BK * AS];
    __shared__ float Bs_[BK * BS];
    int ks = blockIdx.z;
    gemm_core(x, IN, ks * 256,
              W + (size_t)y0 * 64 * TOTAL + ks * 256,
              g_ph + (size_t)ks * B * NN, y0 * 64, 256, false, As_, Bs_);
}

// Far update U(b): g_upd[:, (b+3)*KB..] += h_b @ W^T.  2-launch slack:
// earliest consumer is seq(b+3). Event-ordered, no spinning.
__global__ void __launch_bounds__(256)
upd_kernel(const float* __restrict__ W, int b)
{
    __shared__ float As_[BK * AS];
    __shared__ float Bs_[BK * BS];
    int jb = (b + 3) * KB;
    gemm_core(g_hall, NN, b * KB,
              W + (size_t)jb * TOTAL + IN + b * KB,
              g_upd, jb, KB, true, As_, Bs_);
}

__global__ void zero_upd_kernel()
{
    size_t i = (size_t)blockIdx.x * blockDim.x + threadIdx.x;
    ((float4*)g_upd)[i] = make_float4(0.f, 0.f, 0.f, 0.f);
}

// ---------------------------------------------------------------------------
// Prep: transpose W block tiles into compact [t][node] buffers.
//  c in [0,33)  : g_tri[b][t][i] = (t<i) ? W[b*128+i][IN+b*128+t]*SC : 0
//  c in [33,65) : g_nw [b][t][n] = W[(b+1)*128+n][IN+b*128+t]
//  c in [65,96) : g_nw2[b][t][n] = W[(b+2)*128+n][IN+b*128+t]
// ---------------------------------------------------------------------------
__global__ void __launch_bounds__(256)
prep_kernel(const float* __restrict__ W)
{
    __shared__ float tile[64 * 133];
    int c = blockIdx.x;
    int tid = threadIdx.x;

    int kind = (c < 33) ? 0 : (c < 65) ? 1 : 2;
    int b = (kind == 0) ? c : (kind == 1) ? c - 33 : c - 65;
    const float* src = W + (size_t)((b + kind) * KB) * TOTAL + IN + b * KB;
    float* dst = (kind == 0) ? g_tri + (size_t)b * KB * KB
               : (kind == 1) ? g_nw  + (size_t)b * KB * KB
                             : g_nw2 + (size_t)b * KB * KB;

    for (int h = 0; h < 2; h++) {
        for (int l = tid; l < 64 * 128; l += 256) {
            int r = l >> 7, t = l & 127;
            int i = h * 64 + r;
            float v = src[(size_t)i * TOTAL + t];
            if (kind == 0) v = (t < i) ? v * SC : 0.0f;
            tile[r * 133 + t] = v;
        }
        __syncthreads();
        for (int l = tid; l < 64 * 128; l += 256) {
            int t = l >> 6, n = l & 63;
            dst[t * 128 + h * 64 + n] = tile[n * 133 + t];
        }
        __syncthreads();
    }
}

// ---------------------------------------------------------------------------
// Sequential recurrence + TWO fused near-updates (targets b+1 and b+2).
// 32 CTAs x 512 thr (4 warps/SMSP, validated shape); warp = batch row in the
// recurrence; lane owns nodes 4*lane..4*lane+3.
// smem: tri tile (stride 132) + hs (stride 132) = 76032 B -> co-resides with
// concurrent U/prea CTAs (no placement stalls).
// Near-update: row-quad ownership — warp (rq=wid&3, nq=wid>>2) covers rows
// 4rq..4rq+3 x n-cols 32nq..32nq+31; each (row,n) covered exactly once (no
// reduction). Weights stream from prep-compacted gmem (L2/L1-hot, 128B
// broadcast loads); h pairs from smem; 2x FFMA2 per tile element pair.
// ---------------------------------------------------------------------------
#define HSTR 132

__global__ void __launch_bounds__(512, 1)
seq_kernel(float* __restrict__ out, int b)
{
    extern __shared__ float sm[];
    float* ws = sm;                    // tri tile [t][i], stride 132
    float* hs = sm + 128 * 132;        // h per row, stride HSTR

    int tid  = threadIdx.x;            // 512
    int lane = tid & 31;
    int wid  = tid >> 5;               // 0..15
    int row  = blockIdx.x * 16 + wid;
    int j0   = b * KB;

    // Stage tri tile (fully vectorized, coalesced).
    {
        const float4* tsrc = (const float4*)(g_tri + (size_t)b * KB * KB);
#pragma unroll
        for (int k = 0; k < 8; k++) {
            int idx4 = tid + k * 512;          // 0..4095
            int t  = idx4 >> 5;
            int i4 = (idx4 & 31) * 4;
            *(float4*)&ws[t * 132 + i4] = tsrc[idx4];
        }
    }

    // Init z = (sum of 4 split-K partials [+ near1] [+ near2] [+ far]) * SC.
    float z[4];
    {
        size_t o4 = ((size_t)row * NN + j0) / 4 + lane;
        const float4* p = (const float4*)g_ph;
        size_t stride4 = (size_t)B * NN / 4;
        float4 v0 = p[o4];
        float4 v1 = p[stride4 + o4];
        float4 v2 = p[2 * stride4 + o4];
        float4 v3 = p[3 * stride4 + o4];
        float4 s;
        s.x = (v0.x + v1.x) + (v2.x + v3.x);
        s.y = (v0.y + v1.y) + (v2.y + v3.y);
        s.z = (v0.z + v1.z) + (v2.z + v3.z);
        s.w = (v0.w + v1.w) + (v2.w + v3.w);
        if (b >= 1) {
            float4 nv = ((const float4*)g_n1)[o4];
            s.x += nv.x; s.y += nv.y; s.z += nv.z; s.w += nv.w;
        }
        if (b >= 2) {
            float4 nv = ((const float4*)g_n2)[o4];
            s.x += nv.x; s.y += nv.y; s.z += nv.z; s.w += nv.w;
        }
        if (b >= 3) {
            float4 uv = ((const float4*)g_upd)[o4];
            s.x += uv.x; s.y += uv.y; s.z += uv.z; s.w += uv.w;
        }
        z[0] = s.x * SC; z[1] = s.y * SC; z[2] = s.z * SC; z[3] = s.w * SC;
    }
    __syncthreads();

    // Recurrence. Producer of step t: lane t>>2, component t&3.
    // Software pipeline: w for step t loaded during step t-1's chain.
    const float* wrow = ws + lane * 4;   // + t*132
    float4 w = *(const float4*)(wrow);   // t = 0
    for (int t0 = 0; t0 < 128; t0 += 4) {
#pragma unroll
        for (int tk = 0; tk < 4; tk++) {
            int t = t0 + tk;
            float4 wn = *(const float4*)(wrow + ((t + 1) & 127) * 132);

            float e;  asm("ex2.approx.f32 %0, %1;" : "=f"(e) : "f"(z[tk]));
            float d = e + 1.0f;
            float r;  asm("rcp.approx.f32 %0, %1;" : "=f"(r) : "f"(d));
            float hv = fmaf(-2.0f, r, 1.0f);

            float h = __shfl_sync(0xffffffffu, hv, t >> 2);

            z[0] = fmaf(h, w.x, z[0]);
            z[1] = fmaf(h, w.y, z[1]);
            z[2] = fmaf(h, w.z, z[2]);
            z[3] = fmaf(h, w.w, z[3]);
            w = wn;
        }
    }

    // Finalize own h (z[c] final after own step; later tri entries are 0).
    float h4[4];
#pragma unroll
    for (int c = 0; c < 4; c++) {
        float e;  asm("ex2.approx.f32 %0, %1;" : "=f"(e) : "f"(z[c]));
        float d = e + 1.0f;
        float r;  asm("rcp.approx.f32 %0, %1;" : "=f"(r) : "f"(d));
        h4[c] = fmaf(-2.0f, r, 1.0f);
    }

    if (b == NBLK - 1) {
        float4 o;
        o.x = 1.0f / (1.0f + __expf(-h4[0]));
        o.y = 1.0f / (1.0f + __expf(-h4[1]));
        o.z = 1.0f / (1.0f + __expf(-h4[2]));
        o.w = 1.0f / (1.0f + __expf(-h4[3]));
        *(float4*)(out + (size_t)row * OUT_N + 4 * lane) = o;
        return;
    }

    // Publish h: smem (stride 132, conflict-free) + gmem for U(b).
    *(float4*)&hs[wid * HSTR + 4 * lane] = *(float4*)h4;
    if (b <= NBLK - 4)
        *(float4*)(g_hall + (size_t)row * NN + j0 + 4 * lane) = *(float4*)h4;
    __syncthreads();

    // Row-quad near-updates: out[r][n] = sum_t h[r][t] * Wn[t][n].
    {
        int rq = wid & 3, nq = wid >> 2;
        int r  = 4 * rq + (lane >> 3);
        int n4 = 32 * nq + 4 * (lane & 7);
        int grow = blockIdx.x * 16 + r;
        const float* hrow = hs + r * HSTR;
        int ntgt = (b <= NBLK - 3) ? 2 : 1;

        for (int tgt = 0; tgt < ntgt; tgt++) {
            const float* wsrc = (tgt == 0)
                ? g_nw  + (size_t)b * KB * KB
                : g_nw2 + (size_t)b * KB * KB;
            unsigned long long acc2[2] = {0ull, 0ull};
#pragma unroll 4
            for (int t = 0; t < 128; t += 2) {
                float2 h2 = *(const float2*)&hrow[t];
                ulonglong2 w0 = *(const ulonglong2*)&wsrc[t * 128 + n4];
                ulonglong2 w1 = *(const ulonglong2*)&wsrc[(t + 1) * 128 + n4];
                unsigned long long hp0, hp1;
                asm("mov.b64 %0, {%1, %2};" : "=l"(hp0) : "f"(h2.x), "f"(h2.x));
                asm("mov.b64 %0, {%1, %2};" : "=l"(hp1) : "f"(h2.y), "f"(h2.y));
                asm("fma.rn.f32x2 %0, %1, %2, %0;" : "+l"(acc2[0]) : "l"(w0.x), "l"(hp0));
                asm("fma.rn.f32x2 %0, %1, %2, %0;" : "+l"(acc2[1]) : "l"(w0.y), "l"(hp0));
                asm("fma.rn.f32x2 %0, %1, %2, %0;" : "+l"(acc2[0]) : "l"(w1.x), "l"(hp1));
                asm("fma.rn.f32x2 %0, %1, %2, %0;" : "+l"(acc2[1]) : "l"(w1.y), "l"(hp1));
            }
            float4 o;
            asm("mov.b64 {%0, %1}, %2;" : "=f"(o.x), "=f"(o.y) : "l"(acc2[0]));
            asm("mov.b64 {%0, %1}, %2;" : "=f"(o.z), "=f"(o.w) : "l"(acc2[1]));
            float* dst = (tgt == 0 ? g_n1 : g_n2)
                       + (size_t)grow * NN + j0 + KB * (1 + tgt) + n4;
            *(float4*)dst = o;
        }
    }
}

// ---------------------------------------------------------------------------
// Host: event-only ordering.
//  s2: prep -> evPrep -> zero g_upd; then U(b) after evS[b]
//  s3: prea chunk0 evP0 -> chunk1 evP1 -> chunk2 evP2
//  0 : seq(b) waits {evPrep+evP0@b0, evP1@b2, evP2@b8, evU[b-3]@b>=3}
// ---------------------------------------------------------------------------
extern "C" void kernel_launch(void* const* d_in, const int* in_sizes, int n_in,
                              void* d_out, int out_size)
{
    const float* x = (const float*)d_in[0];   // [512][1024]
    const float* W = (const float*)d_in[1];   // [4224][5248]
    float* out = (float*)d_out;               // [512][128]
    (void)in_sizes; (void)n_in; (void)out_size;

    static bool inited = false;
    static cudaStream_t s2, s3;
    static cudaEvent_t evFork, evPrep, evP0, evP1, evP2, evE2;
    static cudaEvent_t evS[NBLK], evU[NBLK];
    if (!inited) {
        cudaStreamCreateWithFlags(&s2, cudaStreamNonBlocking);
        cudaStreamCreateWithFlags(&s3, cudaStreamNonBlocking);
        cudaEventCreateWithFlags(&evFork, cudaEventDisableTiming);
        cudaEventCreateWithFlags(&evPrep, cudaEventDisableTiming);
        cudaEventCreateWithFlags(&evP0,   cudaEventDisableTiming);
        cudaEventCreateWithFlags(&evP1,   cudaEventDisableTiming);
        cudaEventCreateWithFlags(&evP2,   cudaEventDisableTiming);
        cudaEventCreateWithFlags(&evE2,   cudaEventDisableTiming);
        for (int i = 0; i < NBLK; i++) {
            cudaEventCreateWithFlags(&evS[i], cudaEventDisableTiming);
            cudaEventCreateWithFlags(&evU[i], cudaEventDisableTiming);
        }
        cudaFuncSetAttribute(seq_kernel,
                             cudaFuncAttributeMaxDynamicSharedMemorySize,
                             (128 * 132 + 16 * HSTR) * 4);
        inited = true;
    }

    const int SEQ_SMEM = (128 * 132 + 16 * HSTR) * 4;

    cudaEventRecord(evFork, 0);
    cudaStreamWaitEvent(s2, evFork, 0);
    cudaStreamWaitEvent(s3, evFork, 0);

    // s2: prep tiles (needed by seq(0)), then zero the far accumulator.
    prep_kernel<<<96, 256, 0, s2>>>(W);
    cudaEventRecord(evPrep, s2);
    zero_upd_kernel<<<2112, 256, 0, s2>>>();

    // s3: chunked split-K preA.
    prea_kernel<<<dim3(4, 4, 4),  256, 0, s3>>>(x, W, 0);   // blocks 0-1
    cudaEventRecord(evP0, s3);
    prea_kernel<<<dim3(4, 12, 4), 256, 0, s3>>>(x, W, 4);   // blocks 2-7
    cudaEventRecord(evP1, s3);
    prea_kernel<<<dim3(4, 50, 4), 256, 0, s3>>>(x, W, 16);  // blocks 8-32
    cudaEventRecord(evP2, s3);

    // stream 0: the pipeline.
    for (int b = 0; b < NBLK; b++) {
        if (b == 0) { cudaStreamWaitEvent(0, evPrep, 0);
                      cudaStreamWaitEvent(0, evP0, 0); }
        if (b == 2) cudaStreamWaitEvent(0, evP1, 0);
        if (b == 8) cudaStreamWaitEvent(0, evP2, 0);
        if (b >= 3) cudaStreamWaitEvent(0, evU[b - 3], 0);

        seq_kernel<<<32, 512, SEQ_SMEM, 0>>>(out, b);

        if (b <= NBLK - 4) {   // far update: targets >= b+3
            cudaEventRecord(evS[b], 0);
            cudaStreamWaitEvent(s2, evS[b], 0);
            int jb = (b + 3) * KB;
            upd_kernel<<<dim3(4, (NN - jb) / 64), 256, 0, s2>>>(W, b);
            cudaEventRecord(evU[b], s2);
        }
    }
    cudaEventRecord(evE2, s2);
    cudaStreamWaitEvent(0, evE2, 0);
}

// round 14
// speedup vs baseline: 1.3342x; 1.3342x over previous
#include <cuda_runtime.h>
#include <math.h>

#define B        512
#define IN       1024
#define NN       4224
#define TOTAL    5248
#define KB       128
#define NBLK     33
#define OUT_N    128
#define SC       2.8853900817779268f   // 2*log2(e)
#define HSTR     132

// Device-global scratch (allocation-free rule). Replay-safe: every buffer is
// overwritten each run, or zeroed before accumulation (g_upd).
__device__ float g_ph  [(size_t)4 * B * NN];          // split-K preA partials
__device__ float g_upd [2][(size_t)B * NN];           // far accumulators (parity)
__device__ float g_hall[(size_t)B * NN];              // published h per node
__device__ float g_nacc[(size_t)B * NN];              // near contribution (overwrite)
__device__ float g_tri [(size_t)NBLK * KB * KB];      // [b][t][i] scaled, zeroed t>=i
__device__ float g_nw  [(size_t)(NBLK - 1) * KB * KB];// [b][t][n] block b+1 weights

// ---------------------------------------------------------------------------
// GEMM core (validated R6/R8 form: FFMA2 + pack movs, single-buffered smem).
// C[r][cjbase+n] (+)= sum_k A[r][aoff+k] * Wsub[n*TOTAL + k];  C row stride NN.
// ---------------------------------------------------------------------------
#define BM 128
#define BN 64
#define BK 16
#define AS 132
#define BS 68

__device__ __forceinline__ void
gemm_core(const float* __restrict__ A, int lda, int aoff,
          const float* __restrict__ Wsub, float* __restrict__ C,
          int cjbase, int kc, bool accum, float* As_, float* Bs_)
{
    int m0 = blockIdx.x * BM;
    int n0 = blockIdx.y * BN;
    int tid = threadIdx.x;
    int tx = tid & 15;
    int ty = tid >> 4;

    int a_r = tid >> 1;
    int a_k = (tid & 1) * 8;
    int b_r = tid >> 2;
    int b_k = (tid & 3) * 4;

    unsigned long long acc2[4][4];
#pragma unroll
    for (int i = 0; i < 4; i++)
#pragma unroll
        for (int j = 0; j < 4; j++) acc2[i][j] = 0ull;

    for (int kk = 0; kk < kc; kk += BK) {
        float4 a0 = *(const float4*)(A + (size_t)(m0 + a_r) * lda + aoff + kk + a_k);
        float4 a1 = *(const float4*)(A + (size_t)(m0 + a_r) * lda + aoff + kk + a_k + 4);
        As_[(a_k + 0) * AS + a_r] = a0.x;
        As_[(a_k + 1) * AS + a_r] = a0.y;
        As_[(a_k + 2) * AS + a_r] = a0.z;
        As_[(a_k + 3) * AS + a_r] = a0.w;
        As_[(a_k + 4) * AS + a_r] = a1.x;
        As_[(a_k + 5) * AS + a_r] = a1.y;
        As_[(a_k + 6) * AS + a_r] = a1.z;
        As_[(a_k + 7) * AS + a_r] = a1.w;

        float4 bv = *(const float4*)(Wsub + (size_t)(n0 + b_r) * TOTAL + kk + b_k);
        Bs_[(b_k + 0) * BS + b_r] = bv.x;
        Bs_[(b_k + 1) * BS + b_r] = bv.y;
        Bs_[(b_k + 2) * BS + b_r] = bv.z;
        Bs_[(b_k + 3) * BS + b_r] = bv.w;

        __syncthreads();

#pragma unroll
        for (int k = 0; k < BK; k++) {
            float a[8], b[4];
            *(float4*)&a[0] = *(const float4*)&As_[k * AS + ty * 8];
            *(float4*)&a[4] = *(const float4*)&As_[k * AS + ty * 8 + 4];
            *(float4*)&b[0] = *(const float4*)&Bs_[k * BS + tx * 4];

            unsigned long long ap[4], bb[4];
#pragma unroll
            for (int i = 0; i < 4; i++)
                asm("mov.b64 %0, {%1, %2};"
                    : "=l"(ap[i]) : "f"(a[2 * i]), "f"(a[2 * i + 1]));
#pragma unroll
            for (int j = 0; j < 4; j++)
                asm("mov.b64 %0, {%1, %2};"
                    : "=l"(bb[j]) : "f"(b[j]), "f"(b[j]));

#pragma unroll
            for (int i = 0; i < 4; i++)
#pragma unroll
                for (int j = 0; j < 4; j++)
                    asm("fma.rn.f32x2 %0, %1, %2, %0;"
                        : "+l"(acc2[i][j]) : "l"(ap[i]), "l"(bb[j]));
        }
        __syncthreads();
    }

#pragma unroll
    for (int i = 0; i < 4; i++) {
        float v0[4], v1[4];
#pragma unroll
        for (int j = 0; j < 4; j++)
            asm("mov.b64 {%0, %1}, %2;"
                : "=f"(v0[j]), "=f"(v1[j]) : "l"(acc2[i][j]));

        float* c0 = C + (size_t)(m0 + ty * 8 + 2 * i) * NN + cjbase + n0 + tx * 4;
        float* c1 = c0 + NN;
        if (accum) {
#pragma unroll
            for (int j = 0; j < 4; j++) { c0[j] += v0[j]; c1[j] += v1[j]; }
        } else {
            float4 w0, w1;
            w0.x = v0[0]; w0.y = v0[1]; w0.z = v0[2]; w0.w = v0[3];
            w1.x = v1[0]; w1.y = v1[1]; w1.z = v1[2]; w1.w = v1[3];
            *(float4*)c0 = w0;
            *(float4*)c1 = w1;
        }
    }
}

// preA split-K, CHUNKED over node columns: chunk covers BN-columns
// [y0*64, (y0+gridDim.y)*64). g_ph[z] = x[:, z*256:...] @ W[cols, z*256:...]^T
__global__ void __launch_bounds__(256)
prea_kernel(const float* __restrict__ x, const float* __restrict__ W, int y0)
{
    __shared__ float As_[BK * AS];
    __shared__ float Bs_[BK * BS];
    int ks = blockIdx.z;
    gemm_core(x, IN, ks * 256,
              W + (size_t)y0 * 64 * TOTAL + ks * 256,
              g_ph + (size_t)ks * B * NN, y0 * 64, 256, false, As_, Bs_);
}

// Far update U(b): g_upd[b&1][:, (b+2)*KB..] += h_b @ W^T. Parity-split
// accumulators let U(b) and U(b+1) run concurrently on two streams while
// same-buffer writers stay stream-ordered. Event-ordered, no spinning.
__global__ void __launch_bounds__(256)
upd_kernel(const float* __restrict__ W, int b)
{
    __shared__ float As_[BK * AS];
    __shared__ float Bs_[BK * BS];
    int jb = (b + 2) * KB;
    gemm_core(g_hall, NN, b * KB,
              W + (size_t)jb * TOTAL + IN + b * KB,
              g_upd[b & 1], jb, KB, true, As_, Bs_);
}

__global__ void zero_upd_kernel()   // zero both parity buffers: 4224 CTAs
{
    size_t i = (size_t)blockIdx.x * blockDim.x + threadIdx.x;
    ((float4*)g_upd)[i] = make_float4(0.f, 0.f, 0.f, 0.f);
}

// ---------------------------------------------------------------------------
// Prep: transpose W block tiles into compact [t][node] buffers.
//  c in [0,33)  : g_tri[b][t][i] = (t<i) ? W[b*128+i][IN+b*128+t]*SC : 0
//  c in [33,65) : g_nw [b][t][n] = W[(b+1)*128+n][IN+b*128+t]
// ---------------------------------------------------------------------------
__global__ void __launch_bounds__(256)
prep_kernel(const float* __restrict__ W)
{
    __shared__ float tile[64 * 133];
    int c = blockIdx.x;
    int tid = threadIdx.x;
    bool isTri = (c < NBLK);
    int b = isTri ? c : c - NBLK;
    const float* src = isTri ? W + (size_t)(b * KB) * TOTAL + IN + b * KB
                             : W + (size_t)((b + 1) * KB) * TOTAL + IN + b * KB;
    float* dst = isTri ? g_tri + (size_t)b * KB * KB
                       : g_nw  + (size_t)b * KB * KB;

    for (int h = 0; h < 2; h++) {
        for (int l = tid; l < 64 * 128; l += 256) {
            int r = l >> 7, t = l & 127;
            int i = h * 64 + r;
            float v = src[(size_t)i * TOTAL + t];
            if (isTri) v = (t < i) ? v * SC : 0.0f;
            tile[r * 133 + t] = v;
        }
        __syncthreads();
        for (int l = tid; l < 64 * 128; l += 256) {
            int t = l >> 6, n = l & 63;
            dst[t * 128 + h * 64 + n] = tile[n * 133 + t];
        }
        __syncthreads();
    }
}

// ---------------------------------------------------------------------------
// Sequential recurrence + fused near-update (validated 854us base + row-quad
// near from smem). 32 CTAs x 512 thr (4 warps/SMSP); warp = batch row; lane
// owns nodes 4*lane..4*lane+3.
//  - tri + near tiles staged in smem up front (float4, coalesced).
//  - Recurrence step: explicit next-w prefetch (LDS off the chain), then
//    EX2 -> FADD -> RCP -> FMA -> SHFL -> 4x FMA.
//  - Near-update: row-quad ownership over the SMEM tile — warp (rq,nq)
//    covers rows 4rq+(lane>>3) x cols 32nq+4(lane&7)..; each (row,n) once.
// smem: ws 128*132 | nearw 128*128 | hs 16*132 = 141568 B (1 CTA/SM).
// ---------------------------------------------------------------------------
__global__ void __launch_bounds__(512, 1)
seq_kernel(float* __restrict__ out, int b)
{
    extern __shared__ float sm[];
    float* ws    = sm;                          // tri tile [t][i], stride 132
    float* nearw = sm + 128 * 132;              // near tile [t][n], stride 128
    float* hs    = sm + 128 * 132 + 128 * 128;  // per-row h, stride HSTR

    int tid  = threadIdx.x;         // 512
    int lane = tid & 31;
    int wid  = tid >> 5;            // 0..15
    int row  = blockIdx.x * 16 + wid;
    int j0   = b * KB;

    // Stage tri tile (and near tile when it exists), fully vectorized.
    {
        const float4* tsrc = (const float4*)(g_tri + (size_t)b * KB * KB);
#pragma unroll
        for (int k = 0; k < 8; k++) {
            int idx4 = tid + k * 512;          // 0..4095
            int t  = idx4 >> 5;
            int i4 = (idx4 & 31) * 4;
            *(float4*)&ws[t * 132 + i4] = tsrc[idx4];
        }
        if (b < NBLK - 1) {
            const float4* nsrc = (const float4*)(g_nw + (size_t)b * KB * KB);
#pragma unroll
            for (int k = 0; k < 8; k++) {
                int idx4 = tid + k * 512;
                *(float4*)&nearw[idx4 * 4] = nsrc[idx4];
            }
        }
    }

    // Init z = (sum of 4 split-K partials [+ near] [+ both far bufs]) * SC.
    float z[4];
    {
        size_t o4 = ((size_t)row * NN + j0) / 4 + lane;
        const float4* p = (const float4*)g_ph;
        size_t stride4 = (size_t)B * NN / 4;
        float4 v0 = p[o4];
        float4 v1 = p[stride4 + o4];
        float4 v2 = p[2 * stride4 + o4];
        float4 v3 = p[3 * stride4 + o4];
        float4 s;
        s.x = (v0.x + v1.x) + (v2.x + v3.x);
        s.y = (v0.y + v1.y) + (v2.y + v3.y);
        s.z = (v0.z + v1.z) + (v2.z + v3.z);
        s.w = (v0.w + v1.w) + (v2.w + v3.w);
        if (b >= 1) {
            float4 nv = ((const float4*)g_nacc)[o4];
            s.x += nv.x; s.y += nv.y; s.z += nv.z; s.w += nv.w;
        }
        if (b >= 2) {
            float4 ua = ((const float4*)g_upd[0])[o4];
            float4 ub = ((const float4*)g_upd[1])[o4];
            s.x += ua.x + ub.x; s.y += ua.y + ub.y;
            s.z += ua.z + ub.z; s.w += ua.w + ub.w;
        }
        z[0] = s.x * SC; z[1] = s.y * SC; z[2] = s.z * SC; z[3] = s.w * SC;
    }
    __syncthreads();

    // Recurrence. Producer of step t: lane t>>2, component t&3.
    // Software pipeline: w for step t loaded during step t-1's chain.
    const float* wrow = ws + lane * 4;   // + t*132
    float4 w = *(const float4*)(wrow);   // t = 0
    for (int t0 = 0; t0 < 128; t0 += 4) {
#pragma unroll
        for (int tk = 0; tk < 4; tk++) {
            int t = t0 + tk;
            float4 wn = *(const float4*)(wrow + ((t + 1) & 127) * 132);

            float e;  asm("ex2.approx.f32 %0, %1;" : "=f"(e) : "f"(z[tk]));
            float d = e + 1.0f;
            float r;  asm("rcp.approx.f32 %0, %1;" : "=f"(r) : "f"(d));
            float hv = fmaf(-2.0f, r, 1.0f);

            float h = __shfl_sync(0xffffffffu, hv, t >> 2);

            z[0] = fmaf(h, w.x, z[0]);
            z[1] = fmaf(h, w.y, z[1]);
            z[2] = fmaf(h, w.z, z[2]);
            z[3] = fmaf(h, w.w, z[3]);
            w = wn;
        }
    }

    // Finalize own h (z[c] final after own step; later tri entries are 0).
    float h4[4];
#pragma unroll
    for (int c = 0; c < 4; c++) {
        float e;  asm("ex2.approx.f32 %0, %1;" : "=f"(e) : "f"(z[c]));
        float d = e + 1.0f;
        float r;  asm("rcp.approx.f32 %0, %1;" : "=f"(r) : "f"(d));
        h4[c] = fmaf(-2.0f, r, 1.0f);
    }

    if (b == NBLK - 1) {
        float4 o;
        o.x = 1.0f / (1.0f + __expf(-h4[0]));
        o.y = 1.0f / (1.0f + __expf(-h4[1]));
        o.z = 1.0f / (1.0f + __expf(-h4[2]));
        o.w = 1.0f / (1.0f + __expf(-h4[3]));
        *(float4*)(out + (size_t)row * OUT_N + 4 * lane) = o;
        return;
    }

    // Publish h: smem (stride 132, conflict-free) + gmem for U(b).
    *(float4*)&hs[wid * HSTR + 4 * lane] = *(float4*)h4;
    if (b <= NBLK - 3)
        *(float4*)(g_hall + (size_t)row * NN + j0 + 4 * lane) = *(float4*)h4;
    __syncthreads();

    // Row-quad near-update from SMEM: g_nacc[r][block b+1] = h_r @ Wn^T.
    {
        int rq = wid & 3, nq = wid >> 2;
        int r  = 4 * rq + (lane >> 3);
        int n4 = 32 * nq + 4 * (lane & 7);
        int grow = blockIdx.x * 16 + r;
        const float* hrow = hs + r * HSTR;

        unsigned long long acc2[2] = {0ull, 0ull};
#pragma unroll 4
        for (int t = 0; t < 128; t += 2) {
            float2 h2 = *(const float2*)&hrow[t];
            ulonglong2 w0 = *(const ulonglong2*)&nearw[t * 128 + n4];
            ulonglong2 w1 = *(const ulonglong2*)&nearw[(t + 1) * 128 + n4];
            unsigned long long hp0, hp1;
            asm("mov.b64 %0, {%1, %2};" : "=l"(hp0) : "f"(h2.x), "f"(h2.x));
            asm("mov.b64 %0, {%1, %2};" : "=l"(hp1) : "f"(h2.y), "f"(h2.y));
            asm("fma.rn.f32x2 %0, %1, %2, %0;" : "+l"(acc2[0]) : "l"(w0.x), "l"(hp0));
            asm("fma.rn.f32x2 %0, %1, %2, %0;" : "+l"(acc2[1]) : "l"(w0.y), "l"(hp0));
            asm("fma.rn.f32x2 %0, %1, %2, %0;" : "+l"(acc2[0]) : "l"(w1.x), "l"(hp1));
            asm("fma.rn.f32x2 %0, %1, %2, %0;" : "+l"(acc2[1]) : "l"(w1.y), "l"(hp1));
        }
        float4 o;
        asm("mov.b64 {%0, %1}, %2;" : "=f"(o.x), "=f"(o.y) : "l"(acc2[0]));
        asm("mov.b64 {%0, %1}, %2;" : "=f"(o.z), "=f"(o.w) : "l"(acc2[1]));
        *(float4*)(g_nacc + (size_t)grow * NN + j0 + KB + n4) = o;
    }
}

// ---------------------------------------------------------------------------
// Host: event-only ordering, parity-split U streams.
//  s3: prep -> prea chunk0 evP0 -> chunk1 evP1 -> chunk2 evP2
//  s2: zero g_upd -> evZ; U(even b) after evS[b]
//  s4: wait evZ;          U(odd b)  after evS[b]
//  0 : seq(b) waits {evP0@b0, evP1@b2, evP2@b8, evU[b-2]@b>=2}
// ---------------------------------------------------------------------------
extern "C" void kernel_launch(void* const* d_in, const int* in_sizes, int n_in,
                              void* d_out, int out_size)
{
    const float* x = (const float*)d_in[0];   // [512][1024]
    const float* W = (const float*)d_in[1];   // [4224][5248]
    float* out = (float*)d_out;               // [512][128]
    (void)in_sizes; (void)n_in; (void)out_size;

    static bool inited = false;
    static cudaStream_t s2, s3, s4;
    static cudaEvent_t evFork, evZ, evP0, evP1, evP2, evE2, evE4;
    static cudaEvent_t evS[NBLK], evU[NBLK];
    if (!inited) {
        cudaStreamCreateWithFlags(&s2, cudaStreamNonBlocking);
        cudaStreamCreateWithFlags(&s3, cudaStreamNonBlocking);
        cudaStreamCreateWithFlags(&s4, cudaStreamNonBlocking);
        cudaEventCreateWithFlags(&evFork, cudaEventDisableTiming);
        cudaEventCreateWithFlags(&evZ,    cudaEventDisableTiming);
        cudaEventCreateWithFlags(&evP0,   cudaEventDisableTiming);
        cudaEventCreateWithFlags(&evP1,   cudaEventDisableTiming);
        cudaEventCreateWithFlags(&evP2,   cudaEventDisableTiming);
        cudaEventCreateWithFlags(&evE2,   cudaEventDisableTiming);
        cudaEventCreateWithFlags(&evE4,   cudaEventDisableTiming);
        for (int i = 0; i < NBLK; i++) {
            cudaEventCreateWithFlags(&evS[i], cudaEventDisableTiming);
            cudaEventCreateWithFlags(&evU[i], cudaEventDisableTiming);
        }
        cudaFuncSetAttribute(seq_kernel,
                             cudaFuncAttributeMaxDynamicSharedMemorySize,
                             (128 * 132 + 128 * 128 + 16 * HSTR) * 4);
        inited = true;
    }

    const int SEQ_SMEM = (128 * 132 + 128 * 128 + 16 * HSTR) * 4;

    cudaEventRecord(evFork, 0);
    cudaStreamWaitEvent(s2, evFork, 0);
    cudaStreamWaitEvent(s3, evFork, 0);
    cudaStreamWaitEvent(s4, evFork, 0);

    // s3: prep tiles, then chunked split-K preA.
    prep_kernel<<<2 * NBLK - 1, 256, 0, s3>>>(W);
    prea_kernel<<<dim3(4, 4, 4),  256, 0, s3>>>(x, W, 0);   // blocks 0-1
    cudaEventRecord(evP0, s3);
    prea_kernel<<<dim3(4, 12, 4), 256, 0, s3>>>(x, W, 4);   // blocks 2-7
    cudaEventRecord(evP1, s3);
    prea_kernel<<<dim3(4, 50, 4), 256, 0, s3>>>(x, W, 16);  // blocks 8-32
    cudaEventRecord(evP2, s3);

    // s2: zero both far accumulators; s4 waits for the zero.
    zero_upd_kernel<<<4224, 256, 0, s2>>>();
    cudaEventRecord(evZ, s2);
    cudaStreamWaitEvent(s4, evZ, 0);

    // stream 0: the pipeline.
    for (int b = 0; b < NBLK; b++) {
        if (b == 0) cudaStreamWaitEvent(0, evP0, 0);
        if (b == 2) cudaStreamWaitEvent(0, evP1, 0);
        if (b == 8) cudaStreamWaitEvent(0, evP2, 0);
        if (b >= 2) cudaStreamWaitEvent(0, evU[b - 2], 0);

        seq_kernel<<<32, 512, SEQ_SMEM, 0>>>(out, b);

        if (b <= NBLK - 3) {   // far update: targets >= b+2, parity stream
            cudaEventRecord(evS[b], 0);
            cudaStream_t su = (b & 1) ? s4 : s2;
            cudaStreamWaitEvent(su, evS[b], 0);
            int jb = (b + 2) * KB;
            upd_kernel<<<dim3(4, (NN - jb) / 64), 256, 0, su>>>(W, b);
            cudaEventRecord(evU[b], su);
        }
    }
    cudaEventRecord(evE2, s2);
    cudaEventRecord(evE4, s4);
    cudaStreamWaitEvent(0, evE2, 0);
    cudaStreamWaitEvent(0, evE4, 0);
}

// round 15
// speedup vs baseline: 1.5638x; 1.1721x over previous
#include <cuda_runtime.h>
#include <cuda_bf16.h>
#include <math.h>

#define B        512
#define IN       1024
#define NN       4224
#define TOTAL    5248
#define KB       128
#define NBLK     33
#define OUT_N    128
#define SC       2.8853900817779268f   // 2*log2(e)
#define HSTR     132
#define MSTR     136                   // bf16 elems per smem row (conflict-free)

// Device-global scratch (allocation-free rule). Replay-safe: overwritten each
// run, or zeroed before accumulation (g_upd).
__device__ float g_pre [(size_t)B * NN];              // preA (overwrite)
__device__ float g_upd [(size_t)B * NN];              // far-update accumulator
__device__ float g_hall[(size_t)B * NN];              // published h per node
__device__ float g_nacc[(size_t)B * NN];              // near contribution (overwrite)
__device__ float g_tri [(size_t)NBLK * KB * KB];      // [b][t][i] scaled, zeroed t>=i
__device__ float g_nw  [(size_t)(NBLK - 1) * KB * KB];// [b][t][n] block b+1 weights

// ---------------------------------------------------------------------------
// Tensor-core GEMM with on-the-fly split-bf16 (fp32-grade accuracy):
//   C[r][cjbase+n] (+)= sum_k A[r][aoff+k] * W[n][k]      (W row stride TOTAL)
// computed as Ah*Wh + Al*Wh + Ah*Wl (bf16 hi/lo split, fp32 mma accum).
// CTA 128 thr = 2x2 warps, tile 64x64; K staged in 128-chunks (fits smem).
// Fragments loaded with direct per-lane LDS (canonical m16n8k16 layout);
// stride 136 elems -> all fragment loads bank-conflict-free.
// ---------------------------------------------------------------------------
__global__ void __launch_bounds__(128)
mma_gemm(const float* __restrict__ Ap, int lda, int aoff,
         const float* __restrict__ Wp, int cjbase, int kc,
         int accum, int asel)
{
    extern __shared__ __nv_bfloat16 bsm[];
    __nv_bfloat16* Ah = bsm;
    __nv_bfloat16* Al = bsm + 64 * MSTR;
    __nv_bfloat16* Wh = bsm + 2 * 64 * MSTR;
    __nv_bfloat16* Wl = bsm + 3 * 64 * MSTR;

    const float* A = asel ? g_hall : Ap;
    float*       C = accum ? g_upd : g_pre;

    int m0 = blockIdx.x * 64;
    int n0 = blockIdx.y * 64;
    int tid  = threadIdx.x;
    int lane = tid & 31;
    int wid  = tid >> 5;
    int wm = wid & 1, wn = wid >> 1;     // warp covers (wm*32 m, wn*32 n)
    int g = lane >> 2, t = lane & 3;

    float acc[2][4][4];
#pragma unroll
    for (int i = 0; i < 2; i++)
#pragma unroll
        for (int j = 0; j < 4; j++)
#pragma unroll
            for (int c = 0; c < 4; c++) acc[i][j][c] = 0.0f;

    for (int kk = 0; kk < kc; kk += 128) {
        if (kk) __syncthreads();   // protect previous chunk's reads

        // Stage + split A tile (64 rows x 128 k) and W tile.
#pragma unroll
        for (int i = 0; i < 16; i++) {
            int idx = tid + i * 128;
            int r  = idx >> 5;
            int k4 = (idx & 31) * 4;
            float4 v = *(const float4*)(A + (size_t)(m0 + r) * lda + aoff + kk + k4);
            float f[4] = {v.x, v.y, v.z, v.w};
            __nv_bfloat162 h2, l2;
#pragma unroll
            for (int c = 0; c < 4; c += 2) {
                __nv_bfloat16 h0 = __float2bfloat16(f[c]);
                __nv_bfloat16 h1 = __float2bfloat16(f[c + 1]);
                h2.x = h0; h2.y = h1;
                l2.x = __float2bfloat16(f[c]     - __bfloat162float(h0));
                l2.y = __float2bfloat16(f[c + 1] - __bfloat162float(h1));
                *(__nv_bfloat162*)&Ah[r * MSTR + k4 + c] = h2;
                *(__nv_bfloat162*)&Al[r * MSTR + k4 + c] = l2;
            }
        }
#pragma unroll
        for (int i = 0; i < 16; i++) {
            int idx = tid + i * 128;
            int r  = idx >> 5;
            int k4 = (idx & 31) * 4;
            float4 v = *(const float4*)(Wp + (size_t)(n0 + r) * TOTAL + kk + k4);
            float f[4] = {v.x, v.y, v.z, v.w};
            __nv_bfloat162 h2, l2;
#pragma unroll
            for (int c = 0; c < 4; c += 2) {
                __nv_bfloat16 h0 = __float2bfloat16(f[c]);
                __nv_bfloat16 h1 = __float2bfloat16(f[c + 1]);
                h2.x = h0; h2.y = h1;
                l2.x = __float2bfloat16(f[c]     - __bfloat162float(h0));
                l2.y = __float2bfloat16(f[c + 1] - __bfloat162float(h1));
                *(__nv_bfloat162*)&Wh[r * MSTR + k4 + c] = h2;
                *(__nv_bfloat162*)&Wl[r * MSTR + k4 + c] = l2;
            }
        }
        __syncthreads();

        // 3 split passes: Ah*Wh, Al*Wh, Ah*Wl.
#pragma unroll
        for (int p = 0; p < 3; p++) {
            const __nv_bfloat16* as = (p == 1) ? Al : Ah;
            const __nv_bfloat16* bs = (p == 2) ? Wl : Wh;
#pragma unroll
            for (int k16 = 0; k16 < 128; k16 += 16) {
                unsigned a[2][4], bfr[4][2];
#pragma unroll
                for (int i = 0; i < 2; i++) {
                    int rb = wm * 32 + i * 16;
                    a[i][0] = *(const unsigned*)&as[(rb + g    ) * MSTR + k16 + 2 * t];
                    a[i][1] = *(const unsigned*)&as[(rb + g + 8) * MSTR + k16 + 2 * t];
                    a[i][2] = *(const unsigned*)&as[(rb + g    ) * MSTR + k16 + 8 + 2 * t];
                    a[i][3] = *(const unsigned*)&as[(rb + g + 8) * MSTR + k16 + 8 + 2 * t];
                }
#pragma unroll
                for (int j = 0; j < 4; j++) {
                    int nb = wn * 32 + j * 8;
                    bfr[j][0] = *(const unsigned*)&bs[(nb + g) * MSTR + k16 + 2 * t];
                    bfr[j][1] = *(const unsigned*)&bs[(nb + g) * MSTR + k16 + 8 + 2 * t];
                }
#pragma unroll
                for (int i = 0; i < 2; i++)
#pragma unroll
                    for (int j = 0; j < 4; j++)
                        asm volatile(
                            "mma.sync.aligned.m16n8k16.row.col.f32.bf16.bf16.f32 "
                            "{%0,%1,%2,%3},{%4,%5,%6,%7},{%8,%9},{%0,%1,%2,%3};"
                            : "+f"(acc[i][j][0]), "+f"(acc[i][j][1]),
                              "+f"(acc[i][j][2]), "+f"(acc[i][j][3])
                            : "r"(a[i][0]), "r"(a[i][1]), "r"(a[i][2]), "r"(a[i][3]),
                              "r"(bfr[j][0]), "r"(bfr[j][1]));
            }
        }
    }

    // Epilogue: lane holds (g,2t),(g,2t+1),(g+8,2t),(g+8,2t+1) per 16x8 tile.
#pragma unroll
    for (int i = 0; i < 2; i++)
#pragma unroll
        for (int j = 0; j < 4; j++) {
            int r0 = m0 + wm * 32 + i * 16 + g;
            int c0 = cjbase + n0 + wn * 32 + j * 8 + 2 * t;
            float* p0 = C + (size_t)r0 * NN + c0;
            float* p1 = p0 + (size_t)8 * NN;
            if (accum) {
                float2 o0 = *(float2*)p0, o1 = *(float2*)p1;
                o0.x += acc[i][j][0]; o0.y += acc[i][j][1];
                o1.x += acc[i][j][2]; o1.y += acc[i][j][3];
                *(float2*)p0 = o0; *(float2*)p1 = o1;
            } else {
                *(float2*)p0 = make_float2(acc[i][j][0], acc[i][j][1]);
                *(float2*)p1 = make_float2(acc[i][j][2], acc[i][j][3]);
            }
        }
}

__global__ void zero_upd_kernel()
{
    size_t i = (size_t)blockIdx.x * blockDim.x + threadIdx.x;
    ((float4*)g_upd)[i] = make_float4(0.f, 0.f, 0.f, 0.f);
}

// ---------------------------------------------------------------------------
// Prep: transpose W block tiles into compact [t][node] buffers (unchanged).
// ---------------------------------------------------------------------------
__global__ void __launch_bounds__(256)
prep_kernel(const float* __restrict__ W)
{
    __shared__ float tile[64 * 133];
    int c = blockIdx.x;
    int tid = threadIdx.x;
    bool isTri = (c < NBLK);
    int b = isTri ? c : c - NBLK;
    const float* src = isTri ? W + (size_t)(b * KB) * TOTAL + IN + b * KB
                             : W + (size_t)((b + 1) * KB) * TOTAL + IN + b * KB;
    float* dst = isTri ? g_tri + (size_t)b * KB * KB
                       : g_nw  + (size_t)b * KB * KB;

    for (int h = 0; h < 2; h++) {
        for (int l = tid; l < 64 * 128; l += 256) {
            int r = l >> 7, t = l & 127;
            int i = h * 64 + r;
            float v = src[(size_t)i * TOTAL + t];
            if (isTri) v = (t < i) ? v * SC : 0.0f;
            tile[r * 133 + t] = v;
        }
        __syncthreads();
        for (int l = tid; l < 64 * 128; l += 256) {
            int t = l >> 6, n = l & 63;
            dst[t * 128 + h * 64 + n] = tile[n * 133 + t];
        }
        __syncthreads();
    }
}

// ---------------------------------------------------------------------------
// Sequential recurrence + fused near-update (validated R12/R14 form).
// 32 CTAs x 512 thr (4 warps/SMSP); warp = batch row; lane owns 4*lane..+3.
// smem: ws 128*132 | nearw 128*128 | hs 16*HSTR.
// ---------------------------------------------------------------------------
__global__ void __launch_bounds__(512, 1)
seq_kernel(float* __restrict__ out, int b)
{
    extern __shared__ float sm[];
    float* ws    = sm;
    float* nearw = sm + 128 * 132;
    float* hs    = sm + 128 * 132 + 128 * 128;

    int tid  = threadIdx.x;
    int lane = tid & 31;
    int wid  = tid >> 5;
    int row  = blockIdx.x * 16 + wid;
    int j0   = b * KB;

    {
        const float4* tsrc = (const float4*)(g_tri + (size_t)b * KB * KB);
#pragma unroll
        for (int k = 0; k < 8; k++) {
            int idx4 = tid + k * 512;
            int t  = idx4 >> 5;
            int i4 = (idx4 & 31) * 4;
            *(float4*)&ws[t * 132 + i4] = tsrc[idx4];
        }
        if (b < NBLK - 1) {
            const float4* nsrc = (const float4*)(g_nw + (size_t)b * KB * KB);
#pragma unroll
            for (int k = 0; k < 8; k++) {
                int idx4 = tid + k * 512;
                *(float4*)&nearw[idx4 * 4] = nsrc[idx4];
            }
        }
    }

    float z[4];
    {
        size_t o4 = ((size_t)row * NN + j0) / 4 + lane;
        float4 s = ((const float4*)g_pre)[o4];
        if (b >= 1) {
            float4 nv = ((const float4*)g_nacc)[o4];
            s.x += nv.x; s.y += nv.y; s.z += nv.z; s.w += nv.w;
        }
        if (b >= 2) {
            float4 uv = ((const float4*)g_upd)[o4];
            s.x += uv.x; s.y += uv.y; s.z += uv.z; s.w += uv.w;
        }
        z[0] = s.x * SC; z[1] = s.y * SC; z[2] = s.z * SC; z[3] = s.w * SC;
    }
    __syncthreads();

    const float* wrow = ws + lane * 4;
    float4 w = *(const float4*)(wrow);
    for (int t0 = 0; t0 < 128; t0 += 4) {
#pragma unroll
        for (int tk = 0; tk < 4; tk++) {
            int t = t0 + tk;
            float4 wn = *(const float4*)(wrow + ((t + 1) & 127) * 132);

            float e;  asm("ex2.approx.f32 %0, %1;" : "=f"(e) : "f"(z[tk]));
            float d = e + 1.0f;
            float r;  asm("rcp.approx.f32 %0, %1;" : "=f"(r) : "f"(d));
            float hv = fmaf(-2.0f, r, 1.0f);

            float h = __shfl_sync(0xffffffffu, hv, t >> 2);

            z[0] = fmaf(h, w.x, z[0]);
            z[1] = fmaf(h, w.y, z[1]);
            z[2] = fmaf(h, w.z, z[2]);
            z[3] = fmaf(h, w.w, z[3]);
            w = wn;
        }
    }

    float h4[4];
#pragma unroll
    for (int c = 0; c < 4; c++) {
        float e;  asm("ex2.approx.f32 %0, %1;" : "=f"(e) : "f"(z[c]));
        float d = e + 1.0f;
        float r;  asm("rcp.approx.f32 %0, %1;" : "=f"(r) : "f"(d));
        h4[c] = fmaf(-2.0f, r, 1.0f);
    }

    if (b == NBLK - 1) {
        float4 o;
        o.x = 1.0f / (1.0f + __expf(-h4[0]));
        o.y = 1.0f / (1.0f + __expf(-h4[1]));
        o.z = 1.0f / (1.0f + __expf(-h4[2]));
        o.w = 1.0f / (1.0f + __expf(-h4[3]));
        *(float4*)(out + (size_t)row * OUT_N + 4 * lane) = o;
        return;
    }

    *(float4*)&hs[wid * HSTR + 4 * lane] = *(float4*)h4;
    if (b <= NBLK - 3)
        *(float4*)(g_hall + (size_t)row * NN + j0 + 4 * lane) = *(float4*)h4;
    __syncthreads();

    // Row-quad near-update from SMEM: g_nacc[r][block b+1] = h_r @ Wn^T.
    {
        int rq = wid & 3, nq = wid >> 2;
        int r  = 4 * rq + (lane >> 3);
        int n4 = 32 * nq + 4 * (lane & 7);
        int grow = blockIdx.x * 16 + r;
        const float* hrow = hs + r * HSTR;

        unsigned long long acc2[2] = {0ull, 0ull};
#pragma unroll 4
        for (int t = 0; t < 128; t += 2) {
            float2 h2 = *(const float2*)&hrow[t];
            ulonglong2 w0 = *(const ulonglong2*)&nearw[t * 128 + n4];
            ulonglong2 w1 = *(const ulonglong2*)&nearw[(t + 1) * 128 + n4];
            unsigned long long hp0, hp1;
            asm("mov.b64 %0, {%1, %2};" : "=l"(hp0) : "f"(h2.x), "f"(h2.x));
            asm("mov.b64 %0, {%1, %2};" : "=l"(hp1) : "f"(h2.y), "f"(h2.y));
            asm("fma.rn.f32x2 %0, %1, %2, %0;" : "+l"(acc2[0]) : "l"(w0.x), "l"(hp0));
            asm("fma.rn.f32x2 %0, %1, %2, %0;" : "+l"(acc2[1]) : "l"(w0.y), "l"(hp0));
            asm("fma.rn.f32x2 %0, %1, %2, %0;" : "+l"(acc2[0]) : "l"(w1.x), "l"(hp1));
            asm("fma.rn.f32x2 %0, %1, %2, %0;" : "+l"(acc2[1]) : "l"(w1.y), "l"(hp1));
        }
        float4 o;
        asm("mov.b64 {%0, %1}, %2;" : "=f"(o.x), "=f"(o.y) : "l"(acc2[0]));
        asm("mov.b64 {%0, %1}, %2;" : "=f"(o.z), "=f"(o.w) : "l"(acc2[1]));
        *(float4*)(g_nacc + (size_t)grow * NN + j0 + KB + n4) = o;
    }
}

// ---------------------------------------------------------------------------
// Host: event-only ordering (R12 schedule; GEMMs now tensor-core).
//  s3: prep -> prea chunk0 evP0 -> chunk1 evP1 -> chunk2 evP2
//  s2: zero g_upd; U(b) after evS[b]
//  0 : seq(b) waits {evP0@b0, evP1@b2, evP2@b8, evU[b-2]@b>=2}
// ---------------------------------------------------------------------------
extern "C" void kernel_launch(void* const* d_in, const int* in_sizes, int n_in,
                              void* d_out, int out_size)
{
    const float* x = (const float*)d_in[0];   // [512][1024]
    const float* W = (const float*)d_in[1];   // [4224][5248]
    float* out = (float*)d_out;               // [512][128]
    (void)in_sizes; (void)n_in; (void)out_size;

    static bool inited = false;
    static cudaStream_t s2, s3;
    static cudaEvent_t evFork, evP0, evP1, evP2, evE2;
    static cudaEvent_t evS[NBLK], evU[NBLK];
    if (!inited) {
        cudaStreamCreateWithFlags(&s2, cudaStreamNonBlocking);
        cudaStreamCreateWithFlags(&s3, cudaStreamNonBlocking);
        cudaEventCreateWithFlags(&evFork, cudaEventDisableTiming);
        cudaEventCreateWithFlags(&evP0,   cudaEventDisableTiming);
        cudaEventCreateWithFlags(&evP1,   cudaEventDisableTiming);
        cudaEventCreateWithFlags(&evP2,   cudaEventDisableTiming);
        cudaEventCreateWithFlags(&evE2,   cudaEventDisableTiming);
        for (int i = 0; i < NBLK; i++) {
            cudaEventCreateWithFlags(&evS[i], cudaEventDisableTiming);
            cudaEventCreateWithFlags(&evU[i], cudaEventDisableTiming);
        }
        cudaFuncSetAttribute(seq_kernel,
                             cudaFuncAttributeMaxDynamicSharedMemorySize,
                             (128 * 132 + 128 * 128 + 16 * HSTR) * 4);
        cudaFuncSetAttribute(mma_gemm,
                             cudaFuncAttributeMaxDynamicSharedMemorySize,
                             4 * 64 * MSTR * 2);
        inited = true;
    }

    const int SEQ_SMEM = (128 * 132 + 128 * 128 + 16 * HSTR) * 4;
    const int MMA_SMEM = 4 * 64 * MSTR * 2;   // 69632 B

    cudaEventRecord(evFork, 0);
    cudaStreamWaitEvent(s2, evFork, 0);
    cudaStreamWaitEvent(s3, evFork, 0);

    // s3: prep tiles, then chunked preA (tensor-core, K=1024 per launch).
    prep_kernel<<<2 * NBLK - 1, 256, 0, s3>>>(W);
    mma_gemm<<<dim3(8, 4),  128, MMA_SMEM, s3>>>(x, IN, 0, W, 0, IN, 0, 0);
    cudaEventRecord(evP0, s3);                           // blocks 0-1
    mma_gemm<<<dim3(8, 12), 128, MMA_SMEM, s3>>>(
        x, IN, 0, W + (size_t)256 * TOTAL, 256, IN, 0, 0);
    cudaEventRecord(evP1, s3);                           // blocks 2-7
    mma_gemm<<<dim3(8, 50), 128, MMA_SMEM, s3>>>(
        x, IN, 0, W + (size_t)1024 * TOTAL, 1024, IN, 0, 0);
    cudaEventRecord(evP2, s3);                           // blocks 8-32

    // s2: zero the far accumulator (U(0) serialized behind it on s2).
    zero_upd_kernel<<<2112, 256, 0, s2>>>();

    // stream 0: the pipeline.
    for (int b = 0; b < NBLK; b++) {
        if (b == 0) cudaStreamWaitEvent(0, evP0, 0);
        if (b == 2) cudaStreamWaitEvent(0, evP1, 0);
        if (b == 8) cudaStreamWaitEvent(0, evP2, 0);
        if (b >= 2) cudaStreamWaitEvent(0, evU[b - 2], 0);

        seq_kernel<<<32, 512, SEQ_SMEM, 0>>>(out, b);

        if (b <= NBLK - 3) {   // far update: targets >= b+2
            cudaEventRecord(evS[b], 0);
            cudaStreamWaitEvent(s2, evS[b], 0);
            int jb = (b + 2) * KB;
            mma_gemm<<<dim3(8, (NN - jb) / 64), 128, MMA_SMEM, s2>>>(
                nullptr, NN, b * KB,
                W + (size_t)jb * TOTAL + IN + b * KB,
                jb, KB, /*accum=*/1, /*asel=*/1);
            cudaEventRecord(evU[b], s2);
        }
    }
    cudaEventRecord(evE2, s2);
    cudaStreamWaitEvent(0, evE2, 0);
}

// round 16
// speedup vs baseline: 1.5995x; 1.0229x over previous
#include <cuda_runtime.h>
#include <cuda_bf16.h>
#include <math.h>

#define B        512
#define IN       1024
#define NN       4224
#define TOTAL    5248
#define KB       128
#define NBLK     33
#define OUT_N    128
#define SC       2.8853900817779268f   // 2*log2(e)
#define HSTR     132
#define MSTR     136                   // bf16 elems per smem row (conflict-free)

// Device-global scratch (allocation-free rule). Replay-safe: overwritten each
// run, or zeroed before accumulation (g_upd).
__device__ float g_pre [(size_t)B * NN];              // preA (overwrite)
__device__ float g_upd [(size_t)B * NN];              // far-update accumulator
__device__ float g_hall[(size_t)B * NN];              // published h per node
__device__ float g_nacc[(size_t)B * NN];              // near contribution (overwrite)
__device__ float g_tri [(size_t)NBLK * KB * KB];      // [b][t][i] scaled, zeroed t>=i
__device__ float g_nw  [(size_t)(NBLK - 1) * KB * KB];// [b][t][n] block b+1 weights

// ---------------------------------------------------------------------------
// Tensor-core GEMM with on-the-fly split-bf16 (validated R15 form).
//   C[r][cjbase+n] (+)= sum_k A[r][aoff+k] * W[n][k]      (W row stride TOTAL)
// computed as Ah*Wh + Al*Wh + Ah*Wl (bf16 hi/lo split, fp32 mma accum).
// ---------------------------------------------------------------------------
__global__ void __launch_bounds__(128)
mma_gemm(const float* __restrict__ Ap, int lda, int aoff,
         const float* __restrict__ Wp, int cjbase, int kc,
         int accum, int asel)
{
    extern __shared__ __nv_bfloat16 bsm[];
    __nv_bfloat16* Ah = bsm;
    __nv_bfloat16* Al = bsm + 64 * MSTR;
    __nv_bfloat16* Wh = bsm + 2 * 64 * MSTR;
    __nv_bfloat16* Wl = bsm + 3 * 64 * MSTR;

    const float* A = asel ? g_hall : Ap;
    float*       C = accum ? g_upd : g_pre;

    int m0 = blockIdx.x * 64;
    int n0 = blockIdx.y * 64;
    int tid  = threadIdx.x;
    int lane = tid & 31;
    int wid  = tid >> 5;
    int wm = wid & 1, wn = wid >> 1;
    int g = lane >> 2, t = lane & 3;

    float acc[2][4][4];
#pragma unroll
    for (int i = 0; i < 2; i++)
#pragma unroll
        for (int j = 0; j < 4; j++)
#pragma unroll
            for (int c = 0; c < 4; c++) acc[i][j][c] = 0.0f;

    for (int kk = 0; kk < kc; kk += 128) {
        if (kk) __syncthreads();

#pragma unroll
        for (int i = 0; i < 16; i++) {
            int idx = tid + i * 128;
            int r  = idx >> 5;
            int k4 = (idx & 31) * 4;
            float4 v = *(const float4*)(A + (size_t)(m0 + r) * lda + aoff + kk + k4);
            float f[4] = {v.x, v.y, v.z, v.w};
            __nv_bfloat162 h2, l2;
#pragma unroll
            for (int c = 0; c < 4; c += 2) {
                __nv_bfloat16 h0 = __float2bfloat16(f[c]);
                __nv_bfloat16 h1 = __float2bfloat16(f[c + 1]);
                h2.x = h0; h2.y = h1;
                l2.x = __float2bfloat16(f[c]     - __bfloat162float(h0));
                l2.y = __float2bfloat16(f[c + 1] - __bfloat162float(h1));
                *(__nv_bfloat162*)&Ah[r * MSTR + k4 + c] = h2;
                *(__nv_bfloat162*)&Al[r * MSTR + k4 + c] = l2;
            }
        }
#pragma unroll
        for (int i = 0; i < 16; i++) {
            int idx = tid + i * 128;
            int r  = idx >> 5;
            int k4 = (idx & 31) * 4;
            float4 v = *(const float4*)(Wp + (size_t)(n0 + r) * TOTAL + kk + k4);
            float f[4] = {v.x, v.y, v.z, v.w};
            __nv_bfloat162 h2, l2;
#pragma unroll
            for (int c = 0; c < 4; c += 2) {
                __nv_bfloat16 h0 = __float2bfloat16(f[c]);
                __nv_bfloat16 h1 = __float2bfloat16(f[c + 1]);
                h2.x = h0; h2.y = h1;
                l2.x = __float2bfloat16(f[c]     - __bfloat162float(h0));
                l2.y = __float2bfloat16(f[c + 1] - __bfloat162float(h1));
                *(__nv_bfloat162*)&Wh[r * MSTR + k4 + c] = h2;
                *(__nv_bfloat162*)&Wl[r * MSTR + k4 + c] = l2;
            }
        }
        __syncthreads();

#pragma unroll
        for (int p = 0; p < 3; p++) {
            const __nv_bfloat16* as = (p == 1) ? Al : Ah;
            const __nv_bfloat16* bs = (p == 2) ? Wl : Wh;
#pragma unroll
            for (int k16 = 0; k16 < 128; k16 += 16) {
                unsigned a[2][4], bfr[4][2];
#pragma unroll
                for (int i = 0; i < 2; i++) {
                    int rb = wm * 32 + i * 16;
                    a[i][0] = *(const unsigned*)&as[(rb + g    ) * MSTR + k16 + 2 * t];
                    a[i][1] = *(const unsigned*)&as[(rb + g + 8) * MSTR + k16 + 2 * t];
                    a[i][2] = *(const unsigned*)&as[(rb + g    ) * MSTR + k16 + 8 + 2 * t];
                    a[i][3] = *(const unsigned*)&as[(rb + g + 8) * MSTR + k16 + 8 + 2 * t];
                }
#pragma unroll
                for (int j = 0; j < 4; j++) {
                    int nb = wn * 32 + j * 8;
                    bfr[j][0] = *(const unsigned*)&bs[(nb + g) * MSTR + k16 + 2 * t];
                    bfr[j][1] = *(const unsigned*)&bs[(nb + g) * MSTR + k16 + 8 + 2 * t];
                }
#pragma unroll
                for (int i = 0; i < 2; i++)
#pragma unroll
                    for (int j = 0; j < 4; j++)
                        asm volatile(
                            "mma.sync.aligned.m16n8k16.row.col.f32.bf16.bf16.f32 "
                            "{%0,%1,%2,%3},{%4,%5,%6,%7},{%8,%9},{%0,%1,%2,%3};"
                            : "+f"(acc[i][j][0]), "+f"(acc[i][j][1]),
                              "+f"(acc[i][j][2]), "+f"(acc[i][j][3])
                            : "r"(a[i][0]), "r"(a[i][1]), "r"(a[i][2]), "r"(a[i][3]),
                              "r"(bfr[j][0]), "r"(bfr[j][1]));
            }
        }
    }

#pragma unroll
    for (int i = 0; i < 2; i++)
#pragma unroll
        for (int j = 0; j < 4; j++) {
            int r0 = m0 + wm * 32 + i * 16 + g;
            int c0 = cjbase + n0 + wn * 32 + j * 8 + 2 * t;
            float* p0 = C + (size_t)r0 * NN + c0;
            float* p1 = p0 + (size_t)8 * NN;
            if (accum) {
                float2 o0 = *(float2*)p0, o1 = *(float2*)p1;
                o0.x += acc[i][j][0]; o0.y += acc[i][j][1];
                o1.x += acc[i][j][2]; o1.y += acc[i][j][3];
                *(float2*)p0 = o0; *(float2*)p1 = o1;
            } else {
                *(float2*)p0 = make_float2(acc[i][j][0], acc[i][j][1]);
                *(float2*)p1 = make_float2(acc[i][j][2], acc[i][j][3]);
            }
        }
}

__global__ void zero_upd_kernel()
{
    size_t i = (size_t)blockIdx.x * blockDim.x + threadIdx.x;
    ((float4*)g_upd)[i] = make_float4(0.f, 0.f, 0.f, 0.f);
}

// ---------------------------------------------------------------------------
// Prep: transpose W block tiles into compact [t][node] buffers (unchanged).
// ---------------------------------------------------------------------------
__global__ void __launch_bounds__(256)
prep_kernel(const float* __restrict__ W)
{
    __shared__ float tile[64 * 133];
    int c = blockIdx.x;
    int tid = threadIdx.x;
    bool isTri = (c < NBLK);
    int b = isTri ? c : c - NBLK;
    const float* src = isTri ? W + (size_t)(b * KB) * TOTAL + IN + b * KB
                             : W + (size_t)((b + 1) * KB) * TOTAL + IN + b * KB;
    float* dst = isTri ? g_tri + (size_t)b * KB * KB
                       : g_nw  + (size_t)b * KB * KB;

    for (int h = 0; h < 2; h++) {
        for (int l = tid; l < 64 * 128; l += 256) {
            int r = l >> 7, t = l & 127;
            int i = h * 64 + r;
            float v = src[(size_t)i * TOTAL + t];
            if (isTri) v = (t < i) ? v * SC : 0.0f;
            tile[r * 133 + t] = v;
        }
        __syncthreads();
        for (int l = tid; l < 64 * 128; l += 256) {
            int t = l >> 6, n = l & 63;
            dst[t * 128 + h * 64 + n] = tile[n * 133 + t];
        }
        __syncthreads();
    }
}

__device__ __forceinline__ float tanhz(float zz)
{
    float e;  asm("ex2.approx.f32 %0, %1;" : "=f"(e) : "f"(zz));
    float d = e + 1.0f;
    float r;  asm("rcp.approx.f32 %0, %1;" : "=f"(r) : "f"(d));
    return fmaf(-2.0f, r, 1.0f);
}

// ---------------------------------------------------------------------------
// Sequential recurrence + fused near-update. 32 CTAs x 512 thr; warp = row;
// lane owns nodes 4*lane..4*lane+3.
// GROUPED-PRODUCER recurrence: steps 4g..4g+3 all produced by lane g, so the
// chain runs lane-locally (no SHFL on the chain inside a group); hm = hl*mask
// keeps non-producer lanes inert (their hl is finite garbage * 0), and
// ho = shfl(hl) - hm applies the broadcast to everyone EXCEPT the producer.
// Per-z-component update order is unchanged -> bitwise-identical results.
// ---------------------------------------------------------------------------
__global__ void __launch_bounds__(512, 1)
seq_kernel(float* __restrict__ out, int b)
{
    extern __shared__ float sm[];
    float* ws    = sm;
    float* nearw = sm + 128 * 132;
    float* hs    = sm + 128 * 132 + 128 * 128;

    int tid  = threadIdx.x;
    int lane = tid & 31;
    int wid  = tid >> 5;
    int row  = blockIdx.x * 16 + wid;
    int j0   = b * KB;

    {
        const float4* tsrc = (const float4*)(g_tri + (size_t)b * KB * KB);
#pragma unroll
        for (int k = 0; k < 8; k++) {
            int idx4 = tid + k * 512;
            int t  = idx4 >> 5;
            int i4 = (idx4 & 31) * 4;
            *(float4*)&ws[t * 132 + i4] = tsrc[idx4];
        }
        if (b < NBLK - 1) {
            const float4* nsrc = (const float4*)(g_nw + (size_t)b * KB * KB);
#pragma unroll
            for (int k = 0; k < 8; k++) {
                int idx4 = tid + k * 512;
                *(float4*)&nearw[idx4 * 4] = nsrc[idx4];
            }
        }
    }

    float z[4];
    {
        size_t o4 = ((size_t)row * NN + j0) / 4 + lane;
        float4 s = ((const float4*)g_pre)[o4];
        if (b >= 1) {
            float4 nv = ((const float4*)g_nacc)[o4];
            s.x += nv.x; s.y += nv.y; s.z += nv.z; s.w += nv.w;
        }
        if (b >= 2) {
            float4 uv = ((const float4*)g_upd)[o4];
            s.x += uv.x; s.y += uv.y; s.z += uv.z; s.w += uv.w;
        }
        z[0] = s.x * SC; z[1] = s.y * SC; z[2] = s.z * SC; z[3] = s.w * SC;
    }
    __syncthreads();

    // Grouped-producer recurrence: 32 groups x 4 steps.
    const float* wrow = ws + lane * 4;
#pragma unroll 4
    for (int g = 0; g < 32; g++) {
        const float* wp = wrow + g * 4 * 132;
        float4 w0 = *(const float4*)(wp);
        float4 w1 = *(const float4*)(wp + 132);
        float4 w2 = *(const float4*)(wp + 264);
        float4 w3 = *(const float4*)(wp + 396);
        float mk = (lane == g) ? 1.0f : 0.0f;

        // Phase 1: producer-local chain (inert elsewhere: hm = hl * 0).
        float hl0 = tanhz(z[0]);
        float hm0 = hl0 * mk;
        z[1] = fmaf(hm0, w0.y, z[1]);
        z[2] = fmaf(hm0, w0.z, z[2]);
        z[3] = fmaf(hm0, w0.w, z[3]);
        float hl1 = tanhz(z[1]);
        float hm1 = hl1 * mk;
        z[2] = fmaf(hm1, w1.z, z[2]);
        z[3] = fmaf(hm1, w1.w, z[3]);
        float hl2 = tanhz(z[2]);
        float hm2 = hl2 * mk;
        z[3] = fmaf(hm2, w2.w, z[3]);
        float hl3 = tanhz(z[3]);
        float hm3 = hl3 * mk;

        // Phase 2: broadcast; producer's contribution cancels (ho = 0 there).
        float h0 = __shfl_sync(0xffffffffu, hl0, g) - hm0;
        float h1 = __shfl_sync(0xffffffffu, hl1, g) - hm1;
        float h2 = __shfl_sync(0xffffffffu, hl2, g) - hm2;
        float h3 = __shfl_sync(0xffffffffu, hl3, g) - hm3;

        z[0] = fmaf(h0, w0.x, z[0]); z[1] = fmaf(h0, w0.y, z[1]);
        z[2] = fmaf(h0, w0.z, z[2]); z[3] = fmaf(h0, w0.w, z[3]);
        z[0] = fmaf(h1, w1.x, z[0]); z[1] = fmaf(h1, w1.y, z[1]);
        z[2] = fmaf(h1, w1.z, z[2]); z[3] = fmaf(h1, w1.w, z[3]);
        z[0] = fmaf(h2, w2.x, z[0]); z[1] = fmaf(h2, w2.y, z[1]);
        z[2] = fmaf(h2, w2.z, z[2]); z[3] = fmaf(h2, w2.w, z[3]);
        z[0] = fmaf(h3, w3.x, z[0]); z[1] = fmaf(h3, w3.y, z[1]);
        z[2] = fmaf(h3, w3.z, z[2]); z[3] = fmaf(h3, w3.w, z[3]);
    }

    float h4[4];
#pragma unroll
    for (int c = 0; c < 4; c++) h4[c] = tanhz(z[c]);

    if (b == NBLK - 1) {
        float4 o;
        o.x = 1.0f / (1.0f + __expf(-h4[0]));
        o.y = 1.0f / (1.0f + __expf(-h4[1]));
        o.z = 1.0f / (1.0f + __expf(-h4[2]));
        o.w = 1.0f / (1.0f + __expf(-h4[3]));
        *(float4*)(out + (size_t)row * OUT_N + 4 * lane) = o;
        return;
    }

    *(float4*)&hs[wid * HSTR + 4 * lane] = *(float4*)h4;
    if (b <= NBLK - 3)
        *(float4*)(g_hall + (size_t)row * NN + j0 + 4 * lane) = *(float4*)h4;
    __syncthreads();

    // Row-quad near-update from SMEM: g_nacc[r][block b+1] = h_r @ Wn^T.
    {
        int rq = wid & 3, nq = wid >> 2;
        int r  = 4 * rq + (lane >> 3);
        int n4 = 32 * nq + 4 * (lane & 7);
        int grow = blockIdx.x * 16 + r;
        const float* hrow = hs + r * HSTR;

        unsigned long long acc2[2] = {0ull, 0ull};
#pragma unroll 4
        for (int t = 0; t < 128; t += 2) {
            float2 h2 = *(const float2*)&hrow[t];
            ulonglong2 w0 = *(const ulonglong2*)&nearw[t * 128 + n4];
            ulonglong2 w1 = *(const ulonglong2*)&nearw[(t + 1) * 128 + n4];
            unsigned long long hp0, hp1;
            asm("mov.b64 %0, {%1, %2};" : "=l"(hp0) : "f"(h2.x), "f"(h2.x));
            asm("mov.b64 %0, {%1, %2};" : "=l"(hp1) : "f"(h2.y), "f"(h2.y));
            asm("fma.rn.f32x2 %0, %1, %2, %0;" : "+l"(acc2[0]) : "l"(w0.x), "l"(hp0));
            asm("fma.rn.f32x2 %0, %1, %2, %0;" : "+l"(acc2[1]) : "l"(w0.y), "l"(hp0));
            asm("fma.rn.f32x2 %0, %1, %2, %0;" : "+l"(acc2[0]) : "l"(w1.x), "l"(hp1));
            asm("fma.rn.f32x2 %0, %1, %2, %0;" : "+l"(acc2[1]) : "l"(w1.y), "l"(hp1));
        }
        float4 o;
        asm("mov.b64 {%0, %1}, %2;" : "=f"(o.x), "=f"(o.y) : "l"(acc2[0]));
        asm("mov.b64 {%0, %1}, %2;" : "=f"(o.z), "=f"(o.w) : "l"(acc2[1]));
        *(float4*)(g_nacc + (size_t)grow * NN + j0 + KB + n4) = o;
    }
}

// ---------------------------------------------------------------------------
// Host: event-only ordering. prep moved OFF the prea path:
//  s2: prep -> evPrep -> zero g_upd; then U(b) after evS[b]
//  s3: prea chunk0 evP0 -> chunk1 evP1 -> chunk2 evP2   (starts immediately)
//  0 : seq(b) waits {evPrep+evP0@b0, evP1@b2, evP2@b8, evU[b-2]@b>=2}
// ---------------------------------------------------------------------------
extern "C" void kernel_launch(void* const* d_in, const int* in_sizes, int n_in,
                              void* d_out, int out_size)
{
    const float* x = (const float*)d_in[0];   // [512][1024]
    const float* W = (const float*)d_in[1];   // [4224][5248]
    float* out = (float*)d_out;               // [512][128]
    (void)in_sizes; (void)n_in; (void)out_size;

    static bool inited = false;
    static cudaStream_t s2, s3;
    static cudaEvent_t evFork, evPrep, evP0, evP1, evP2, evE2;
    static cudaEvent_t evS[NBLK], evU[NBLK];
    if (!inited) {
        cudaStreamCreateWithFlags(&s2, cudaStreamNonBlocking);
        cudaStreamCreateWithFlags(&s3, cudaStreamNonBlocking);
        cudaEventCreateWithFlags(&evFork, cudaEventDisableTiming);
        cudaEventCreateWithFlags(&evPrep, cudaEventDisableTiming);
        cudaEventCreateWithFlags(&evP0,   cudaEventDisableTiming);
        cudaEventCreateWithFlags(&evP1,   cudaEventDisableTiming);
        cudaEventCreateWithFlags(&evP2,   cudaEventDisableTiming);
        cudaEventCreateWithFlags(&evE2,   cudaEventDisableTiming);
        for (int i = 0; i < NBLK; i++) {
            cudaEventCreateWithFlags(&evS[i], cudaEventDisableTiming);
            cudaEventCreateWithFlags(&evU[i], cudaEventDisableTiming);
        }
        cudaFuncSetAttribute(seq_kernel,
                             cudaFuncAttributeMaxDynamicSharedMemorySize,
                             (128 * 132 + 128 * 128 + 16 * HSTR) * 4);
        cudaFuncSetAttribute(mma_gemm,
                             cudaFuncAttributeMaxDynamicSharedMemorySize,
                             4 * 64 * MSTR * 2);
        inited = true;
    }

    const int SEQ_SMEM = (128 * 132 + 128 * 128 + 16 * HSTR) * 4;
    const int MMA_SMEM = 4 * 64 * MSTR * 2;   // 69632 B

    cudaEventRecord(evFork, 0);
    cudaStreamWaitEvent(s2, evFork, 0);
    cudaStreamWaitEvent(s3, evFork, 0);

    // s2: prep tiles (seq(0) gate), then zero the far accumulator.
    prep_kernel<<<2 * NBLK - 1, 256, 0, s2>>>(W);
    cudaEventRecord(evPrep, s2);
    zero_upd_kernel<<<2112, 256, 0, s2>>>();

    // s3: chunked preA (tensor-core), starts immediately.
    mma_gemm<<<dim3(8, 4),  128, MMA_SMEM, s3>>>(x, IN, 0, W, 0, IN, 0, 0);
    cudaEventRecord(evP0, s3);                           // blocks 0-1
    mma_gemm<<<dim3(8, 12), 128, MMA_SMEM, s3>>>(
        x, IN, 0, W + (size_t)256 * TOTAL, 256, IN, 0, 0);
    cudaEventRecord(evP1, s3);                           // blocks 2-7
    mma_gemm<<<dim3(8, 50), 128, MMA_SMEM, s3>>>(
        x, IN, 0, W + (size_t)1024 * TOTAL, 1024, IN, 0, 0);
    cudaEventRecord(evP2, s3);                           // blocks 8-32

    // stream 0: the pipeline.
    for (int b = 0; b < NBLK; b++) {
        if (b == 0) { cudaStreamWaitEvent(0, evPrep, 0);
                      cudaStreamWaitEvent(0, evP0, 0); }
        if (b == 2) cudaStreamWaitEvent(0, evP1, 0);
        if (b == 8) cudaStreamWaitEvent(0, evP2, 0);
        if (b >= 2) cudaStreamWaitEvent(0, evU[b - 2], 0);

        seq_kernel<<<32, 512, SEQ_SMEM, 0>>>(out, b);

        if (b <= NBLK - 3) {   // far update: targets >= b+2
            cudaEventRecord(evS[b], 0);
            cudaStreamWaitEvent(s2, evS[b], 0);
            int jb = (b + 2) * KB;
            mma_gemm<<<dim3(8, (NN - jb) / 64), 128, MMA_SMEM, s2>>>(
                nullptr, NN, b * KB,
                W + (size_t)jb * TOTAL + IN + b * KB,
                jb, KB, /*accum=*/1, /*asel=*/1);
            cudaEventRecord(evU[b], s2);
        }
    }
    cudaEventRecord(evE2, s2);
    cudaStreamWaitEvent(0, evE2, 0);
}